// round 17
// baseline (speedup 1.0000x reference)
#include <cuda_runtime.h>
#include <cuda_fp16.h>
#include <cstdint>

#define IN_      512
#define OUT_     512
#define NB_      16
#define M_TOTAL  1024
#define TM       32
#define TN       32
#define NTHREADS 128
#define KHALF    256
#define NCH      4              // 64-wide k-chunks per K-half

#define X_ELEMS  (M_TOTAL * IN_)      // 524,288
#define XBLOCKS  256                  // x-convert / out-zero blocks

// smem: A planes [0,16K), B planes [16K,32K), 4KB per 32x64 fp16 plane
#define PLANE      4096
#define A_OFFB(c)  ((uint32_t)(c) * PLANE)
#define B_OFFB(c)  (16384u + (uint32_t)(c) * PLANE)
#define SMEM_TOTAL 32768

__device__ __align__(16) __half g_x16[X_ELEMS];
__device__ int g_rows[NB_ * M_TOTAL];
__device__ int g_cnt[NB_];

// ---------------- PTX helpers ----------------
__device__ __forceinline__ uint32_t smem_u32(const void* p) {
    uint32_t a;
    asm("{ .reg .u64 t; cvta.to.shared.u64 t, %1; cvt.u32.u64 %0, t; }" : "=r"(a) : "l"(p));
    return a;
}
__device__ __forceinline__ void ldsm4(uint32_t* r, uint32_t addr) {
    asm volatile("ldmatrix.sync.aligned.m8n8.x4.shared.b16 {%0,%1,%2,%3}, [%4];"
        : "=r"(r[0]), "=r"(r[1]), "=r"(r[2]), "=r"(r[3]) : "r"(addr));
}
__device__ __forceinline__ void mma_fp16(float* c, const uint32_t* a, uint32_t b0, uint32_t b1) {
    asm volatile("mma.sync.aligned.m16n8k16.row.col.f32.f16.f16.f32 "
        "{%0,%1,%2,%3}, {%4,%5,%6,%7}, {%8,%9}, {%0,%1,%2,%3};"
        : "+f"(c[0]), "+f"(c[1]), "+f"(c[2]), "+f"(c[3])
        : "r"(a[0]), "r"(a[1]), "r"(a[2]), "r"(a[3]), "r"(b0), "r"(b1));
}
__device__ __forceinline__ void cp_async16(uint32_t dst, const void* src, int srcsize) {
    asm volatile("cp.async.cg.shared.global [%0], [%1], 16, %2;"
        :: "r"(dst), "l"(src), "r"(srcsize) : "memory");
}
#define CP_COMMIT() asm volatile("cp.async.commit_group;" ::: "memory")

__device__ __forceinline__ uint32_t h2bits(__half2 h) {
    return *reinterpret_cast<uint32_t*>(&h);
}
__device__ __forceinline__ uint2 cvt2(float4 v) {
    uint2 o;
    o.x = h2bits(__floats2half2_rn(v.x, v.y));
    o.y = h2bits(__floats2half2_rn(v.z, v.w));
    return o;
}

// ---------------- prep: x -> fp16, out -> 0, binning ----------------
__global__ __launch_bounds__(256) void prep_kernel(
    const float* __restrict__ x, const int* __restrict__ sel, float* __restrict__ out)
{
    if (blockIdx.x == XBLOCKS) {
        // global order-free binning (row results are order-independent)
        int tid = threadIdx.x;
        if (tid < NB_) g_cnt[tid] = 0;
        __syncthreads();
        #pragma unroll
        for (int i = 0; i < M_TOTAL / 256; i++) {
            int idx = tid + i * 256;
            int g = sel[idx];
            int p = atomicAdd(&g_cnt[g], 1);
            g_rows[g * M_TOTAL + p] = idx;
        }
        return;
    }
    size_t i = ((size_t)blockIdx.x * 256 + threadIdx.x) * 8;
    float4 a = *(const float4*)(x + i);
    float4 b = *(const float4*)(x + i + 4);
    uint4 o;
    o.x = h2bits(__floats2half2_rn(a.x, a.y));
    o.y = h2bits(__floats2half2_rn(a.z, a.w));
    o.z = h2bits(__floats2half2_rn(b.x, b.y));
    o.w = h2bits(__floats2half2_rn(b.z, b.w));
    *(uint4*)(g_x16 + i) = o;
    // zero the output (same index range: 512K floats)
    float4 z = make_float4(0.f, 0.f, 0.f, 0.f);
    *(float4*)(out + i)     = z;
    *(float4*)(out + i + 4) = z;
}

// compute one 64-k chunk (T literal 0..3)
#define COMPUTE_CHUNK(T) do {                                                  \
    const uint32_t a_b = sm_b + A_OFFB(T) + a_off;                             \
    const uint32_t b_b = sm_b + B_OFFB(T) + b_off;                             \
    _Pragma("unroll")                                                          \
    for (int s = 0; s < 4; s++) {                                              \
        uint32_t koff = ((uint32_t)(khf + s * 32)) ^ swx;                      \
        uint32_t ah[4], bh[4];                                                 \
        ldsm4(ah, a_b + koff);                                                 \
        ldsm4(bh, b_b + koff);                                                 \
        mma_fp16(acc[0], ah, bh[0], bh[2]);                                    \
        mma_fp16(acc[1], ah, bh[1], bh[3]);                                    \
    }                                                                          \
} while (0)

// ---------------- split-K grouped GEMM (fp16 HMMA) ----------------
__global__ __launch_bounds__(NTHREADS, 5) void gemm_kernel(
    const float* __restrict__ w,      // (NB, OUT, IN) fp32
    const float* __restrict__ bias,   // (NB, OUT)
    float* __restrict__ out)          // (1024, OUT), pre-zeroed
{
    extern __shared__ __align__(128) uint8_t smem[];

    const int tid = threadIdx.x;
    const int lid = tid & 31, wid = tid >> 5;
    const int warp_m = wid & 1;        // 2 m-warps x 16 rows
    const int warp_n = wid >> 1;       // 2 n-warps x 16 cols
    const int g  = blockIdx.y;
    const int n0 = blockIdx.x * TN;
    const int mz = blockIdx.z >> 1;    // m-slice (4 slices of 32)
    const int kh = blockIdx.z & 1;     // k-half (0 or 1)

    const int cnt = g_cnt[g];
    if (mz * TM >= cnt) return;

    const uint32_t sm_b = smem_u32(smem);

    // ---- A staging consts (R14-verified): row = tid>>2, two 16B units ----
    const int st_row = tid >> 2;
    const int u0     = (tid & 3) * 2;
    const uint32_t a_msk = (uint32_t)(st_row & 7) << 4;
    const uint32_t dstA0 = ((uint32_t)(st_row * 128 + u0 * 16))       ^ a_msk;
    const uint32_t dstA1 = ((uint32_t)(st_row * 128 + (u0 + 1) * 16)) ^ a_msk;

    // ---- B staging consts (R13-verified): rbase = tid>>4, 4 rows, uint2 ----
    const int rbase = tid >> 4;                   // 0..7
    const int c4    = (tid & 15) * 4;             // fp32 col within 64-chunk
    const uint32_t st_sw = (uint32_t)((tid & 15) * 8) ^ (uint32_t)(rbase * 16);
    const float* __restrict__ bsrc =
        w + ((size_t)g * OUT_ + n0) * IN_ + kh * KHALF + c4;

    // ---- ldmatrix consts (R13-R15-verified) ----
    const uint32_t swx   = (uint32_t)(lid & 7) * 16;
    const uint32_t khf   = (uint32_t)(lid >> 4) * 16;
    const uint32_t a_off = (uint32_t)(warp_m * 16 + (lid & 15)) * 128;
    const uint32_t b_off = (uint32_t)(warp_n * 16 + (lid & 15)) * 128;

    bool first = true;

    #pragma unroll 1
    for (int m0 = mz * TM; m0 < cnt; m0 += 4 * TM) {
        // A source row (invalid rows -> zero fill via srcsize=0)
        int mrow = m0 + st_row;
        int valid = (mrow < cnt);
        int r = valid ? g_rows[g * M_TOTAL + mrow] : 0;
        const __half* __restrict__ a_src =
            g_x16 + (size_t)r * IN_ + kh * KHALF + u0 * 8;
        const int asz = valid ? 16 : 0;

        // ---- issue A: group0 = chunks {0,1}, group1 = chunks {2,3} ----
        #pragma unroll
        for (int c = 0; c < 2; c++) {
            cp_async16(sm_b + A_OFFB(c) + dstA0, a_src + c * 64,     asz);
            cp_async16(sm_b + A_OFFB(c) + dstA1, a_src + c * 64 + 8, asz);
        }
        CP_COMMIT();
        #pragma unroll
        for (int c = 2; c < 4; c++) {
            cp_async16(sm_b + A_OFFB(c) + dstA0, a_src + c * 64,     asz);
            cp_async16(sm_b + A_OFFB(c) + dstA1, a_src + c * 64 + 8, asz);
        }
        CP_COMMIT();

        float4 bv1[8];
        if (first) {
            // B chunks 0,1: load 8 float4 (MLP), convert, store planes 0,1
            float4 bv0[8];
            #pragma unroll
            for (int j = 0; j < 4; j++) {
                const float* s = bsrc + (size_t)(rbase + j * 8) * IN_;
                bv0[j * 2 + 0] = *(const float4*)(s);
                bv0[j * 2 + 1] = *(const float4*)(s + 64);
            }
            #pragma unroll
            for (int j = 0; j < 4; j++) {
                uint32_t soff = (uint32_t)((rbase + j * 8) * 128) + st_sw;
                *(uint2*)(smem + B_OFFB(0) + soff) = cvt2(bv0[j * 2 + 0]);
                *(uint2*)(smem + B_OFFB(1) + soff) = cvt2(bv0[j * 2 + 1]);
            }
            // B chunks 2,3: issue LDGs now (latency drains during barrier)
            #pragma unroll
            for (int j = 0; j < 4; j++) {
                const float* s = bsrc + (size_t)(rbase + j * 8) * IN_ + 128;
                bv1[j * 2 + 0] = *(const float4*)(s);
                bv1[j * 2 + 1] = *(const float4*)(s + 64);
            }
        }

        asm volatile("cp.async.wait_group 1;" ::: "memory");
        __syncthreads();            // A chunks 0,1 + B planes 0,1 visible

        if (first) {                // stage B planes 2,3 (read after bar2)
            #pragma unroll
            for (int j = 0; j < 4; j++) {
                uint32_t soff = (uint32_t)((rbase + j * 8) * 128) + st_sw;
                *(uint2*)(smem + B_OFFB(2) + soff) = cvt2(bv1[j * 2 + 0]);
                *(uint2*)(smem + B_OFFB(3) + soff) = cvt2(bv1[j * 2 + 1]);
            }
            first = false;
        }

        float acc[2][4] = {};
        COMPUTE_CHUNK(0);
        COMPUTE_CHUNK(1);

        asm volatile("cp.async.wait_group 0;" ::: "memory");
        __syncthreads();            // A chunks 2,3 + B planes 2,3 visible

        COMPUTE_CHUNK(2);
        COMPUTE_CHUNK(3);

        // ---- epilogue: commutative atomic reduction (2 adds per element) ----
        {
            int gq = lid >> 2, tq = lid & 3;
            int m_lo = m0 + warp_m * 16 + gq;
            int r0 = (m_lo     < cnt) ? g_rows[g * M_TOTAL + m_lo]     : -1;
            int r1 = (m_lo + 8 < cnt) ? g_rows[g * M_TOTAL + m_lo + 8] : -1;
            #pragma unroll
            for (int nf = 0; nf < 2; nf++) {
                int col = warp_n * 16 + nf * 8 + tq * 2;
                float2 bb = make_float2(0.f, 0.f);
                if (kh == 0) bb = *(const float2*)&bias[g * OUT_ + n0 + col];
                if (r0 >= 0) {
                    float* p = out + (size_t)r0 * OUT_ + n0 + col;
                    atomicAdd(p,     acc[nf][0] + bb.x);
                    atomicAdd(p + 1, acc[nf][1] + bb.y);
                }
                if (r1 >= 0) {
                    float* p = out + (size_t)r1 * OUT_ + n0 + col;
                    atomicAdd(p,     acc[nf][2] + bb.x);
                    atomicAdd(p + 1, acc[nf][3] + bb.y);
                }
            }
        }
        __syncthreads();   // A planes fully consumed before next pass's cp.async
    }
}

// ---------------------------------------------------------------------------
extern "C" void kernel_launch(void* const* d_in, const int* in_sizes, int n_in,
                              void* d_out, int out_size) {
    const float* tensor = (const float*)d_in[0];   // (B,S,K,IN) fp32
    const int*   sel    = (const int*)  d_in[1];   // (B,S,K) int32
    const float* weight = (const float*)d_in[2];   // (NB,OUT,IN) fp32
    const float* bias   = (const float*)d_in[3];   // (NB,OUT) fp32
    float*       out    = (float*)d_out;           // (B,S,K,OUT) fp32

    cudaFuncSetAttribute(gemm_kernel, cudaFuncAttributeMaxDynamicSharedMemorySize, SMEM_TOTAL);
    prep_kernel<<<XBLOCKS + 1, 256>>>(tensor, sel, out);
    dim3 grid(OUT_ / TN, NB_, 8);   // (16, 16, 4 mz x 2 kh) = 2048 CTAs
    gemm_kernel<<<grid, NTHREADS, SMEM_TOTAL>>>(weight, bias, out);
}